// round 9
// baseline (speedup 1.0000x reference)
#include <cuda_runtime.h>
#include <cuda_bf16.h>

#define KK 7
#define C1 21
#define C1S 24              // padded class stride (mult of 4 -> float4 loads)
#define NBINS 49            // KK*KK
#define HF 128
#define WF 128
#define PLANE (HF*WF)       // 16384
#define FEAT_STRIDE 30
#define MAX_YSTEP 9         // rois: ystep <= 9 by construction

// P layout: [g][y][slot][ccp], slot = x+1 (slot 0 all-zero so xs=0 left corner
// needs no predication), ccp = 0..23 (21..23 pad, always 0).
#define ROWP (129*C1S)      // 3096 (mult of 4)
#define PLANEP (HF*ROWP)    // 396288 floats per bin-group

// ~77.7 MB scratch (zero-initialized static storage)
__device__ float g_prefix[NBINS * PLANEP];

// K1 smem tile: [cc][x], row stride 132 words (16B-aligned, conflict-free STS.128)
#define SROW 132

// ---------------------------------------------------------------------------
// K1: NCHW -> [g][y][x+1][ccp] transpose + inclusive x-prefix-sum.
// Block per (g, y), 224 threads = 7 warps x 3 class rows (exact).
// Scan in registers (fmap via __ldcs: single-use stream, keep P in L2),
// conflict-free STS.128 into [cc][x] tile, transposed copy-out with
// strength-reduced (slot, cc) indexing (no divs in the loop).
// ---------------------------------------------------------------------------
__global__ __launch_bounds__(224)
void psroi_transpose_scan_kernel(const float* __restrict__ fmap,
                                 float* __restrict__ P)
{
    const int g = blockIdx.x >> 7;        // 0..48
    const int y = blockIdx.x & 127;       // 0..127
    const int t = threadIdx.x;
    const int warp = t >> 5;
    const int lane = t & 31;

    __shared__ __align__(16) float tile[C1 * SROW];   // inclusive prefix, [cc][x]

    #pragma unroll
    for (int r = 0; r < 3; ++r) {
        const int cc = warp * 3 + r;      // 0..20 exact
        const float4* src = (const float4*)(fmap + (size_t)(g * C1 + cc) * PLANE + y * WF);
        float4 v = __ldcs(src + lane);
        float a0 = v.x;
        float a1 = a0 + v.y;
        float a2 = a1 + v.z;
        float a3 = a2 + v.w;
        float s = a3;
        #pragma unroll
        for (int d = 1; d < 32; d <<= 1) {
            float u = __shfl_up_sync(0xffffffff, s, d);
            if (lane >= d) s += u;
        }
        float excl = __shfl_up_sync(0xffffffff, s, 1);
        if (lane == 0) excl = 0.0f;

        *(float4*)&tile[cc * SROW + 4 * lane] =
            make_float4(excl + a0, excl + a1, excl + a2, excl + a3);
    }
    __syncthreads();

    // copy-out: 3096 words [slot*24 + ccp]; slot0 column and ccp>=21 pads are 0
    float* dst = P + (unsigned)g * PLANEP + (unsigned)y * ROWP;
    unsigned slot = (unsigned)t / C1S;
    unsigned cc   = (unsigned)t - slot * C1S;
    for (unsigned o = t; o < (unsigned)ROWP; o += 224) {
        float v = 0.0f;
        if (slot != 0u && cc < C1)
            v = tile[cc * SROW + slot - 1];
        dst[o] = v;
        // o += 224 = 9*24 + 8
        slot += 9u; cc += 8u;
        if (cc >= (unsigned)C1S) { cc -= (unsigned)C1S; slot += 1u; }
    }
}

// ---------------------------------------------------------------------------
// K2: pooling + mean + softmax. Block per ROI, 320 threads.
// Threads 0..48 precompute per-bin right-corner base offsets into smem.
// Threads 0..293: (g, quad qq) -> one float4 corner load covers 4 classes.
// Predicated dy unroll with uniform ystep branch. Warp 0: mean + softmax.
// ---------------------------------------------------------------------------
__global__ __launch_bounds__(320, 5)
void psroi_pool_kernel(const float* __restrict__ P,
                       const int* __restrict__ rois,
                       float* __restrict__ out)
{
    const int n = blockIdx.x;
    const int t = threadIdx.x;

    __shared__ unsigned binoff[NBINS];
    __shared__ __align__(16) float pool[NBINS * C1S];

    const int4 rr = __ldg(((const int4*)rois) + n);
    const unsigned ymin = (unsigned)rr.x / FEAT_STRIDE;
    const unsigned xmin = (unsigned)rr.y / FEAT_STRIDE;
    const unsigned ymax = (unsigned)rr.z / FEAT_STRIDE;
    const unsigned xmax = (unsigned)rr.w / FEAT_STRIDE;
    const int ystep = (int)((ymax - ymin) / KK);
    const int xstep = (int)((xmax - xmin) / KK);
    const bool has_area = (ystep > 0) && (xstep > 0);
    const float inv_area = has_area ? (1.0f / (float)(ystep * xstep)) : 0.0f;

    if (t < NBINS) {
        const unsigned j = (unsigned)t / KK;
        const unsigned l = (unsigned)t - j * KK;
        const unsigned ys = ymin + j * (unsigned)ystep;
        const unsigned xe = xmin + (l + 1u) * (unsigned)xstep;   // right slot
        binoff[t] = (unsigned)t * PLANEP + ys * ROWP + xe * C1S;
    }
    __syncthreads();

    if (t < NBINS * 6) {
        const unsigned g  = (unsigned)t / 6u;
        const unsigned qq = (unsigned)t - g * 6u;
        const unsigned co = 4u * qq;                 // class quad base
        float ax = 0.0f, ay = 0.0f, az = 0.0f, aw = 0.0f;
        if (has_area) {
            const unsigned dlw  = (unsigned)xstep * C1S;
            const unsigned offR = binoff[g] + co;
            const unsigned offL = offR - dlw;        // left slot (slot0 = zeros)
            if (ystep <= 4) {
                #pragma unroll
                for (int dy = 0; dy < 4; ++dy)
                    if (dy < ystep) {
                        float4 r  = __ldg((const float4*)(P + offR + dy * ROWP));
                        float4 lf = __ldg((const float4*)(P + offL + dy * ROWP));
                        ax += r.x - lf.x; ay += r.y - lf.y;
                        az += r.z - lf.z; aw += r.w - lf.w;
                    }
            } else {
                #pragma unroll
                for (int dy = 0; dy < MAX_YSTEP; ++dy)
                    if (dy < ystep) {
                        float4 r  = __ldg((const float4*)(P + offR + dy * ROWP));
                        float4 lf = __ldg((const float4*)(P + offL + dy * ROWP));
                        ax += r.x - lf.x; ay += r.y - lf.y;
                        az += r.z - lf.z; aw += r.w - lf.w;
                    }
            }
        }
        *(float4*)&pool[g * C1S + co] =
            make_float4(ax * inv_area, ay * inv_area, az * inv_area, aw * inv_area);
    }
    __syncthreads();

    // Per-class mean over 49 bins + softmax over 21 classes (warp 0 only)
    if (t < 32) {
        float v = -1e30f;
        if (t < C1) {
            float s = 0.0f;
            #pragma unroll
            for (int g = 0; g < NBINS; ++g)
                s += pool[g * C1S + t];
            v = s * (1.0f / (float)NBINS);
        }
        float mx = v;
        #pragma unroll
        for (int o = 16; o; o >>= 1)
            mx = fmaxf(mx, __shfl_xor_sync(0xffffffff, mx, o));
        float e = (t < C1) ? __expf(v - mx) : 0.0f;
        float sm = e;
        #pragma unroll
        for (int o = 16; o; o >>= 1)
            sm += __shfl_xor_sync(0xffffffff, sm, o);
        if (t < C1)
            out[n * C1 + t] = e / sm;
    }
}

extern "C" void kernel_launch(void* const* d_in, const int* in_sizes, int n_in,
                              void* d_out, int out_size)
{
    const float* fmap = (const float*)d_in[0];   // (1, 1029, 128, 128) fp32
    const int*   rois = (const int*)d_in[1];     // (N, 4) int32
    float* out = (float*)d_out;                  // (N, 21) fp32
    const int n_rois = in_sizes[1] / 4;

    float* P;
    cudaGetSymbolAddress((void**)&P, g_prefix);

    psroi_transpose_scan_kernel<<<NBINS * HF, 224>>>(fmap, P);
    psroi_pool_kernel<<<n_rois, 320>>>(P, rois, out);
}

// round 10
// speedup vs baseline: 1.0037x; 1.0037x over previous
#include <cuda_runtime.h>
#include <cuda_bf16.h>

#define KK 7
#define C1 21
#define C1S 24              // padded class stride in P (mult of 4 -> float4 loads)
#define NBINS 49            // KK*KK
#define HF 128
#define WF 128
#define PLANE (HF*WF)       // 16384
#define FEAT_STRIDE 30
#define MAX_YSTEP 9         // rois: ystep <= 9 by construction

// P layout: [g][y][slot][ccp], slot = x+1. Slot 0 and ccp=21..23 are NEVER
// written: static __device__ storage is zero-initialized, so they stay 0 and
// serve as the zero column / pad classes K2 relies on.
#define ROWP (129*C1S)      // 3096
#define PLANEP (HF*ROWP)    // 396288 floats per bin-group

__device__ float g_prefix[NBINS * PLANEP];

// K1 smem tile: [x][cc] with pitch 25 (lane store stride 100 = 4 mod 32 -> 4-way)
#define TPITCH 25

// ---------------------------------------------------------------------------
// K1: NCHW -> [g][y][x+1][ccp] transpose + inclusive x-prefix-sum.
// Block per (g, y), 224 threads = 7 warps x 3 class rows (exact).
// Register warp scan (fmap via __ldcs), scatter into stride-25 tile (4-way),
// copy-out writes ONLY real words (2688) with strength-reduced indexing.
// ---------------------------------------------------------------------------
__global__ __launch_bounds__(224)
void psroi_transpose_scan_kernel(const float* __restrict__ fmap,
                                 float* __restrict__ P)
{
    const int g = blockIdx.x >> 7;        // 0..48
    const int y = blockIdx.x & 127;       // 0..127
    const int t = threadIdx.x;
    const int warp = t >> 5;
    const int lane = t & 31;

    __shared__ float tile[WF * TPITCH];   // [x][cc], 12.5 KB

    #pragma unroll
    for (int r = 0; r < 3; ++r) {
        const int cc = warp * 3 + r;      // 0..20 exact
        const float4* src = (const float4*)(fmap + (size_t)(g * C1 + cc) * PLANE + y * WF);
        float4 v = __ldcs(src + lane);
        float a0 = v.x;
        float a1 = a0 + v.y;
        float a2 = a1 + v.z;
        float a3 = a2 + v.w;
        float s = a3;
        #pragma unroll
        for (int d = 1; d < 32; d <<= 1) {
            float u = __shfl_up_sync(0xffffffff, s, d);
            if (lane >= d) s += u;
        }
        float excl = __shfl_up_sync(0xffffffff, s, 1);
        if (lane == 0) excl = 0.0f;

        const int xb = 4 * lane;          // x = xb..xb+3, inclusive prefixes
        tile[(xb + 0) * TPITCH + cc] = excl + a0;
        tile[(xb + 1) * TPITCH + cc] = excl + a1;
        tile[(xb + 2) * TPITCH + cc] = excl + a2;
        tile[(xb + 3) * TPITCH + cc] = excl + a3;
    }
    __syncthreads();

    // copy-out: 2688 real words; task i -> (x = i/21, cc = i%21),
    // dst word = (x+1)*24 + cc. Strength-reduced: i += 224 => x += 10, cc += 14.
    float* dst = P + (unsigned)g * PLANEP + (unsigned)y * ROWP;
    unsigned x  = (unsigned)t / C1;
    unsigned cc = (unsigned)t - x * C1;
    for (unsigned i = t; i < (unsigned)(WF * C1); i += 224) {
        dst[(x + 1u) * C1S + cc] = tile[x * TPITCH + cc];
        x += 10u; cc += 14u;
        if (cc >= (unsigned)C1) { cc -= (unsigned)C1; x += 1u; }
    }
}

// ---------------------------------------------------------------------------
// K2: pooling + mean + softmax. Block per ROI, 320 threads.
// Threads 0..48 precompute per-bin right-corner base offsets into smem.
// Threads 0..293: (g, quad qq) -> one float4 corner load covers 4 classes.
// Predicated dy unroll with uniform ystep branch. Warp 0: mean + softmax.
// ---------------------------------------------------------------------------
__global__ __launch_bounds__(320, 5)
void psroi_pool_kernel(const float* __restrict__ P,
                       const int* __restrict__ rois,
                       float* __restrict__ out)
{
    const int n = blockIdx.x;
    const int t = threadIdx.x;

    __shared__ unsigned binoff[NBINS];
    __shared__ __align__(16) float pool[NBINS * C1S];

    const int4 rr = __ldg(((const int4*)rois) + n);
    const unsigned ymin = (unsigned)rr.x / FEAT_STRIDE;
    const unsigned xmin = (unsigned)rr.y / FEAT_STRIDE;
    const unsigned ymax = (unsigned)rr.z / FEAT_STRIDE;
    const unsigned xmax = (unsigned)rr.w / FEAT_STRIDE;
    const int ystep = (int)((ymax - ymin) / KK);
    const int xstep = (int)((xmax - xmin) / KK);
    const bool has_area = (ystep > 0) && (xstep > 0);
    const float inv_area = has_area ? (1.0f / (float)(ystep * xstep)) : 0.0f;

    if (t < NBINS) {
        const unsigned j = (unsigned)t / KK;
        const unsigned l = (unsigned)t - j * KK;
        const unsigned ys = ymin + j * (unsigned)ystep;
        const unsigned xe = xmin + (l + 1u) * (unsigned)xstep;   // right slot
        binoff[t] = (unsigned)t * PLANEP + ys * ROWP + xe * C1S;
    }
    __syncthreads();

    if (t < NBINS * 6) {
        const unsigned g  = (unsigned)t / 6u;
        const unsigned qq = (unsigned)t - g * 6u;
        const unsigned co = 4u * qq;                 // class quad base
        float ax = 0.0f, ay = 0.0f, az = 0.0f, aw = 0.0f;
        if (has_area) {
            const unsigned dlw  = (unsigned)xstep * C1S;
            const unsigned offR = binoff[g] + co;
            const unsigned offL = offR - dlw;        // left slot (slot0 = zeros)
            if (ystep <= 4) {
                #pragma unroll
                for (int dy = 0; dy < 4; ++dy)
                    if (dy < ystep) {
                        float4 r  = __ldg((const float4*)(P + offR + dy * ROWP));
                        float4 lf = __ldg((const float4*)(P + offL + dy * ROWP));
                        ax += r.x - lf.x; ay += r.y - lf.y;
                        az += r.z - lf.z; aw += r.w - lf.w;
                    }
            } else {
                #pragma unroll
                for (int dy = 0; dy < MAX_YSTEP; ++dy)
                    if (dy < ystep) {
                        float4 r  = __ldg((const float4*)(P + offR + dy * ROWP));
                        float4 lf = __ldg((const float4*)(P + offL + dy * ROWP));
                        ax += r.x - lf.x; ay += r.y - lf.y;
                        az += r.z - lf.z; aw += r.w - lf.w;
                    }
            }
        }
        *(float4*)&pool[g * C1S + co] =
            make_float4(ax * inv_area, ay * inv_area, az * inv_area, aw * inv_area);
    }
    __syncthreads();

    // Per-class mean over 49 bins + softmax over 21 classes (warp 0 only)
    if (t < 32) {
        float v = -1e30f;
        if (t < C1) {
            float s = 0.0f;
            #pragma unroll
            for (int g = 0; g < NBINS; ++g)
                s += pool[g * C1S + t];
            v = s * (1.0f / (float)NBINS);
        }
        float mx = v;
        #pragma unroll
        for (int o = 16; o; o >>= 1)
            mx = fmaxf(mx, __shfl_xor_sync(0xffffffff, mx, o));
        float e = (t < C1) ? __expf(v - mx) : 0.0f;
        float sm = e;
        #pragma unroll
        for (int o = 16; o; o >>= 1)
            sm += __shfl_xor_sync(0xffffffff, sm, o);
        if (t < C1)
            out[n * C1 + t] = e / sm;
    }
}

extern "C" void kernel_launch(void* const* d_in, const int* in_sizes, int n_in,
                              void* d_out, int out_size)
{
    const float* fmap = (const float*)d_in[0];   // (1, 1029, 128, 128) fp32
    const int*   rois = (const int*)d_in[1];     // (N, 4) int32
    float* out = (float*)d_out;                  // (N, 21) fp32
    const int n_rois = in_sizes[1] / 4;

    float* P;
    cudaGetSymbolAddress((void**)&P, g_prefix);

    psroi_transpose_scan_kernel<<<NBINS * HF, 224>>>(fmap, P);
    psroi_pool_kernel<<<n_rois, 320>>>(P, rois, out);
}